// round 17
// baseline (speedup 1.0000x reference)
#include <cuda_runtime.h>
#include <cstdint>

// ---------------------------------------------------------------------------
// CML2DWithStats, round 17: r15 base (cluster-4, DS = beta*drive smem tile,
// split cluster barrier, PULL halo) + ADJACENT pairs (quad per thread) with
// middle-row register sharing: 6 row-loads per step instead of 8.
//
//   g_{t+1} = clamp( conv3x3( m_t, K' ) + BETA*drive ),  m = g*(1-g)
//   K' = R*(1-BETA)*(EPS*K + (1-EPS)*delta_center)
//
// Cluster (4,1,1) per plane; rank = 64-row strip. Per-CTA smem:
//   MB0/MB1: two 66-row mapped buffers (rows 0..63 own, 64/65 halo slots)
//   DS: 64-row beta*drive tile (filled once at init)
// Thread (tx,ty) owns quad rows q..q+3, q = 4*ty. Step:
//   1. halo pull into local slot (ty0: neighbor row63 -> slot64; ty15:
//      neighbor row0 -> slot65; fetching warp is the slot's sole reader)
//   2. phase 1 = boundary-side pair (low pair for ty!=15, HIGH pair for
//      ty15) -- middle rows q+1,q+2 saved in registers; ty0 consumes its
//      halo slot LAST (hides DSMEM latency)
//   3. cluster.arrive (boundary rows 0,1,62,63 of Mout released)
//   4. phase 2 = other pair, reusing the 2 saved rows (2 loads only)
//   5. __syncthreads   6. cluster.wait (~free)
// ---------------------------------------------------------------------------

#define R_PARAM  3.9f
#define EPS_P    0.3f
#define BETA_P   0.15f
#define NSTEPS   15
#define CLAMP_LO 1e-4f
#define CLAMP_HI (1.0f - 1e-4f)

constexpr int W      = 256;
constexpr int RCTA   = 64;
constexpr int NSTRIP = 4;
constexpr int BROWS  = 66;                 // 64 own + 2 halo slots
constexpr int TXN    = 32;
constexpr int TYN    = 16;
constexpr int NTHR   = TXN * TYN;          // 512
constexpr int NPLANE = W * 256;
constexpr long long NTOT = 16LL * 8 * NPLANE;
constexpr int BUF        = BROWS * W;                  // 16896 floats
constexpr int DS_OFF     = 2 * BUF;                    // DS tile offset (floats)
constexpr int SMEM_BYTES = (2 * BUF + RCTA * W) * 4;   // 200704 B

__device__ __forceinline__ float clampg(float v) {
    return fminf(fmaxf(v, CLAMP_LO), CLAMP_HI);
}

__device__ __forceinline__ uint32_t smem_u32(const void* p) {
    uint32_t a;
    asm("{ .reg .u64 t; cvta.to.shared.u64 t, %1; cvt.u32.u64 %0, t; }"
        : "=r"(a) : "l"(p));
    return a;
}

__device__ __forceinline__ float4 dsmem_ld4(uint32_t my_addr, uint32_t rank) {
    uint32_t ra; float4 v;
    asm volatile("mapa.shared::cluster.u32 %0, %1, %2;"
                 : "=r"(ra) : "r"(my_addr), "r"(rank));
    asm volatile("ld.shared::cluster.v4.f32 {%0, %1, %2, %3}, [%4];"
                 : "=f"(v.x), "=f"(v.y), "=f"(v.z), "=f"(v.w) : "r"(ra));
    return v;
}

#define CLUSTER_ARRIVE() \
    asm volatile("barrier.cluster.arrive.aligned;" ::: "memory")
#define CLUSTER_WAIT() \
    asm volatile("barrier.cluster.wait.aligned;"   ::: "memory")
#define CLUSTER_BAR()  do { CLUSTER_ARRIVE(); CLUSTER_WAIT(); } while (0)

__global__ void __launch_bounds__(NTHR, 1) __cluster_dims__(NSTRIP, 1, 1)
cml_quad_kernel(const float* __restrict__ drive,
                const float* __restrict__ Klocal,
                float* __restrict__ out)
{
    extern __shared__ float sm[];
    float* MB0 = sm;
    float* MB1 = sm + BUF;
    float* DS  = sm + DS_OFF;              // 64 rows of beta*drive

    const int tx = threadIdx.x;
    const int ty = threadIdx.y;
    const int strip = blockIdx.x;          // cluster rank 0..3
    const int c     = blockIdx.y;
    const int b     = blockIdx.z;
    const int x4    = tx * 4;
    const int x0    = tx * 8;
    const int rbase = strip * RCTA;
    const int q     = 4 * ty;              // quad base row (0..60)

    // Folded kernel K' = R*(1-BETA)*(EPS*K + (1-EPS)*delta)
    float kk[3][3];
    {
        const float* kc = Klocal + c * 9;
        #pragma unroll
        for (int j = 0; j < 3; ++j)
            #pragma unroll
            for (int i = 0; i < 3; ++i) {
                float v = EPS_P * kc[j * 3 + i];
                if (j == 1 && i == 1) v += (1.0f - EPS_P);
                kk[j][i] = R_PARAM * (1.0f - BETA_P) * v;
            }
    }

    const long long plane = (long long)(b * 8 + c) * NPLANE;
    const float* dpl = drive + plane;

    // ---- init: MB0 rows 0..63 <- mapped(drive); DS <- beta*drive ----
    #pragma unroll
    for (int k = 0; k < 4; ++k) {
        int r = ty + TYN * k;                   // 0..63
        const float* dr = dpl + (long long)(rbase + r) * W + x0;
        float4 dA = *reinterpret_cast<const float4*>(dr);
        float4 dB = *reinterpret_cast<const float4*>(dr + 4);

        float4 mA, mB;
        mA.x = fmaf(-dA.x, dA.x, dA.x);  mA.y = fmaf(-dA.y, dA.y, dA.y);
        mA.z = fmaf(-dA.z, dA.z, dA.z);  mA.w = fmaf(-dA.w, dA.w, dA.w);
        mB.x = fmaf(-dB.x, dB.x, dB.x);  mB.y = fmaf(-dB.y, dB.y, dB.y);
        mB.z = fmaf(-dB.z, dB.z, dB.z);  mB.w = fmaf(-dB.w, dB.w, dB.w);
        float* p0 = MB0 + r * W;
        *reinterpret_cast<float4*>(p0 + x4)       = mA;
        *reinterpret_cast<float4*>(p0 + 128 + x4) = mB;

        float4 bA = make_float4(BETA_P * dA.x, BETA_P * dA.y,
                                BETA_P * dA.z, BETA_P * dA.w);
        float4 bB = make_float4(BETA_P * dB.x, BETA_P * dB.y,
                                BETA_P * dB.z, BETA_P * dB.w);
        float* pd = DS + r * W;
        *reinterpret_cast<float4*>(pd + x4)       = bA;
        *reinterpret_cast<float4*>(pd + 128 + x4) = bB;
    }
    CLUSTER_BAR();

    // stats: low pair (q,q+1) and high pair (q+2,q+3). [rowInPair*8 + i]
    float sumL[16], ssqL[16], sumH[16], ssqH[16];
    #pragma unroll
    for (int i = 0; i < 16; ++i) {
        sumL[i] = 0.f; ssqL[i] = 0.f; sumH[i] = 0.f; ssqH[i] = 0.f;
    }

    #define ACCROW(acc, cc)                                                    \
        {                                                                      \
            float c0 = (cc)[0], c1 = (cc)[1], c2 = (cc)[2];                    \
            acc[0] = fmaf(c0, lm, fmaf(c1, m0, fmaf(c2, m1, acc[0])));         \
            acc[1] = fmaf(c0, m0, fmaf(c1, m1, fmaf(c2, m2, acc[1])));         \
            acc[2] = fmaf(c0, m1, fmaf(c1, m2, fmaf(c2, m3, acc[2])));         \
            acc[3] = fmaf(c0, m2, fmaf(c1, m3, fmaf(c2, m4, acc[3])));         \
            acc[4] = fmaf(c0, m3, fmaf(c1, m4, fmaf(c2, m5, acc[4])));         \
            acc[5] = fmaf(c0, m4, fmaf(c1, m5, fmaf(c2, m6, acc[5])));         \
            acc[6] = fmaf(c0, m5, fmaf(c1, m6, fmaf(c2, m7, acc[6])));         \
            acc[7] = fmaf(c0, m6, fmaf(c1, m7, fmaf(c2, rm, acc[7])));         \
        }

    #define LOAD_MROW(Min, slot)                                               \
        const float* rp = (Min) + (slot) * W;                                  \
        float4 qa = *reinterpret_cast<const float4*>(rp + x4);                 \
        float4 qb = *reinterpret_cast<const float4*>(rp + 128 + x4);           \
        float m0 = qa.x, m1 = qa.y, m2 = qa.z, m3 = qa.w;                      \
        float m4 = qb.x, m5 = qb.y, m6 = qb.z, m7 = qb.w;                      \
        float lm = __shfl_up_sync(0xffffffffu, m7, 1);                         \
        float rm = __shfl_down_sync(0xffffffffu, m0, 1);                       \
        if (tx == 0)  lm = 0.f;                                                \
        if (tx == 31) rm = 0.f;

    #define SAVE_MROW(sv)                                                      \
        { sv[0]=m0; sv[1]=m1; sv[2]=m2; sv[3]=m3;                              \
          sv[4]=m4; sv[5]=m5; sv[6]=m6; sv[7]=m7; }

    #define RESTORE_MROW(sv)                                                   \
        float m0=sv[0], m1=sv[1], m2=sv[2], m3=sv[3];                          \
        float m4=sv[4], m5=sv[5], m6=sv[6], m7=sv[7];                          \
        float lm = __shfl_up_sync(0xffffffffu, m7, 1);                         \
        float rm = __shfl_down_sync(0xffffffffu, m0, 1);                       \
        if (tx == 0)  lm = 0.f;                                                \
        if (tx == 31) rm = 0.f;

    #define LOAD_DS_ACC(rr, acc)                                               \
        {                                                                      \
            const float* pd = DS + (rr) * W;                                   \
            float4 aA = *reinterpret_cast<const float4*>(pd + x4);             \
            float4 aB = *reinterpret_cast<const float4*>(pd + 128 + x4);       \
            acc[0] = aA.x;  acc[1] = aA.y;  acc[2] = aA.z;  acc[3] = aA.w;     \
            acc[4] = aB.x;  acc[5] = aB.y;  acc[6] = aB.z;  acc[7] = aB.w;     \
        }

    #define PAIR_EPILOG(Mout, orow, acc0, acc1, sumP, ssqP)                    \
        {                                                                      \
            _Pragma("unroll")                                                  \
            for (int i = 0; i < 8; ++i) {                                      \
                float g = clampg(acc0[i]);                                     \
                sumP[i] += g;  ssqP[i] = fmaf(g, g, ssqP[i]);                  \
                acc0[i] = fmaf(-g, g, g);                                      \
            }                                                                  \
            _Pragma("unroll")                                                  \
            for (int i = 0; i < 8; ++i) {                                      \
                float g = clampg(acc1[i]);                                     \
                sumP[i + 8] += g;  ssqP[i + 8] = fmaf(g, g, ssqP[i + 8]);      \
                acc1[i] = fmaf(-g, g, g);                                      \
            }                                                                  \
            float* op0 = (Mout) + (orow) * W;                                  \
            float* op1 = (Mout) + ((orow) + 1) * W;                            \
            *reinterpret_cast<float4*>(op0 + x4)       = make_float4(acc0[0], acc0[1], acc0[2], acc0[3]); \
            *reinterpret_cast<float4*>(op0 + 128 + x4) = make_float4(acc0[4], acc0[5], acc0[6], acc0[7]); \
            *reinterpret_cast<float4*>(op1 + x4)       = make_float4(acc1[0], acc1[1], acc1[2], acc1[3]); \
            *reinterpret_cast<float4*>(op1 + 128 + x4) = make_float4(acc1[4], acc1[5], acc1[6], acc1[7]); \
        }

    // halo pull into local slots of Min; fetching warp is sole reader.
    #define HALO_PROLOGUE(Min)                                                 \
        {                                                                      \
            if (ty == 0) {                                                     \
                float4 h0 = make_float4(0.f, 0.f, 0.f, 0.f), h1 = h0;          \
                if (strip > 0) {                                               \
                    uint32_t a = smem_u32((Min) + 63 * W + x4);                \
                    h0 = dsmem_ld4(a,       (uint32_t)(strip - 1));            \
                    h1 = dsmem_ld4(a + 512, (uint32_t)(strip - 1));            \
                }                                                              \
                *reinterpret_cast<float4*>((Min) + 64 * W + x4)       = h0;    \
                *reinterpret_cast<float4*>((Min) + 64 * W + 128 + x4) = h1;    \
            } else if (ty == TYN - 1) {                                        \
                float4 h0 = make_float4(0.f, 0.f, 0.f, 0.f), h1 = h0;          \
                if (strip < NSTRIP - 1) {                                      \
                    uint32_t a = smem_u32((Min) + x4);                         \
                    h0 = dsmem_ld4(a,       (uint32_t)(strip + 1));            \
                    h1 = dsmem_ld4(a + 512, (uint32_t)(strip + 1));            \
                }                                                              \
                *reinterpret_cast<float4*>((Min) + 65 * W + x4)       = h0;    \
                *reinterpret_cast<float4*>((Min) + 65 * W + 128 + x4) = h1;    \
            }                                                                  \
        }

    // ---- steps 0..13 ----
    #pragma unroll 1
    for (int t = 0; t < NSTEPS - 1; ++t) {
        float* Min  = (t & 1) ? MB1 : MB0;
        float* Mout = (t & 1) ? MB0 : MB1;

        HALO_PROLOGUE(Min)

        float sA[8], sB[8];   // saved middle rows q+1, q+2

        // ---- phase 1: boundary-side pair (ty15 runs HIGH pair first) ----
        if (ty != TYN - 1) {
            float acc0[8], acc1[8];                // rows q, q+1
            LOAD_DS_ACC(q, acc0)
            LOAD_DS_ACC(q + 1, acc1)
            if (ty != 0) { LOAD_MROW(Min, q - 1)  ACCROW(acc0, kk[0]) }
            { LOAD_MROW(Min, q)      ACCROW(acc0, kk[1]) ACCROW(acc1, kk[0]) }
            { LOAD_MROW(Min, q + 1)  SAVE_MROW(sA)
                                     ACCROW(acc0, kk[2]) ACCROW(acc1, kk[1]) }
            { LOAD_MROW(Min, q + 2)  SAVE_MROW(sB) ACCROW(acc1, kk[2]) }
            if (ty == 0) { LOAD_MROW(Min, 64)  ACCROW(acc0, kk[0]) }  // halo last
            PAIR_EPILOG(Mout, q, acc0, acc1, sumL, ssqL)
        } else {
            float acc0[8], acc1[8];                // rows q+2, q+3 (= 62, 63)
            LOAD_DS_ACC(q + 2, acc0)
            LOAD_DS_ACC(q + 3, acc1)
            { LOAD_MROW(Min, q + 1)  SAVE_MROW(sA) ACCROW(acc0, kk[0]) }
            { LOAD_MROW(Min, q + 2)  SAVE_MROW(sB)
                                     ACCROW(acc0, kk[1]) ACCROW(acc1, kk[0]) }
            { LOAD_MROW(Min, q + 3)  ACCROW(acc0, kk[2]) ACCROW(acc1, kk[1]) }
            { LOAD_MROW(Min, 65)     ACCROW(acc1, kk[2]) }            // halo last
            PAIR_EPILOG(Mout, q + 2, acc0, acc1, sumH, ssqH)
        }
        CLUSTER_ARRIVE();                  // boundary rows 0,1,62,63 released

        // ---- phase 2: other pair, reusing saved rows (2 loads only) ----
        if (ty != TYN - 1) {
            float acc0[8], acc1[8];                // rows q+2, q+3
            LOAD_DS_ACC(q + 2, acc0)
            LOAD_DS_ACC(q + 3, acc1)
            { RESTORE_MROW(sA)       ACCROW(acc0, kk[0]) }            // row q+1
            { RESTORE_MROW(sB)       ACCROW(acc0, kk[1]) ACCROW(acc1, kk[0]) } // q+2
            { LOAD_MROW(Min, q + 3)  ACCROW(acc0, kk[2]) ACCROW(acc1, kk[1]) }
            { LOAD_MROW(Min, q + 4)  ACCROW(acc1, kk[2]) }            // q+4 <= 60
            PAIR_EPILOG(Mout, q + 2, acc0, acc1, sumH, ssqH)
        } else {
            float acc0[8], acc1[8];                // rows q, q+1 (= 60, 61)
            LOAD_DS_ACC(q, acc0)
            LOAD_DS_ACC(q + 1, acc1)
            { LOAD_MROW(Min, q - 1)  ACCROW(acc0, kk[0]) }            // row 59
            { LOAD_MROW(Min, q)      ACCROW(acc0, kk[1]) ACCROW(acc1, kk[0]) }
            { RESTORE_MROW(sA)       ACCROW(acc0, kk[2]) ACCROW(acc1, kk[1]) } // 61
            { RESTORE_MROW(sB)       ACCROW(acc1, kk[2]) }            // 62
            PAIR_EPILOG(Mout, q, acc0, acc1, sumL, ssqL)
        }
        __syncthreads();                   // intra-CTA ordering of Mout
        CLUSTER_WAIT();                    // ~free by now
    }

    // ---- final step t=14 (reads MB0): compute quad, write 5 outputs ----
    {
        float* Min = MB0;
        const float inv = 1.0f / (float)NSTEPS;
        const int upSlot = (ty == 0)       ? 64 : (q - 1);
        const int dnSlot = (ty == TYN - 1) ? 65 : (q + 4);

        HALO_PROLOGUE(Min)

        #pragma unroll
        for (int pp = 0; pp < 2; ++pp) {
            const int r0  = pp ? (q + 2) : q;          // pair base row
            const int ir0 = rbase + r0;                 // image row
            float* sumP = pp ? sumH : sumL;
            float* ssqP = pp ? ssqH : ssqL;
            const int R0 = pp ? (q + 1) : upSlot;
            const int R1 = pp ? (q + 2) : q;
            const int R2 = pp ? (q + 3) : (q + 1);
            const int R3 = pp ? dnSlot  : (q + 2);

            float acc0[8] = {0.f,0.f,0.f,0.f,0.f,0.f,0.f,0.f};
            float acc1[8] = {0.f,0.f,0.f,0.f,0.f,0.f,0.f,0.f};
            { LOAD_MROW(Min, R0)  ACCROW(acc0, kk[0]) }
            { LOAD_MROW(Min, R1)  ACCROW(acc0, kk[1]) ACCROW(acc1, kk[0]) }
            { LOAD_MROW(Min, R2)  ACCROW(acc0, kk[2]) ACCROW(acc1, kk[1]) }
            { LOAD_MROW(Min, R3)  ACCROW(acc1, kk[2]) }

            #pragma unroll
            for (int half = 0; half < 2; ++half) {
                float* acc = half ? acc1 : acc0;
                const int off = half * 8;
                const int ir  = ir0 + half;
                long long idx = plane + (long long)ir * W + x0;

                // raw drive from global (needed exactly for delta)
                const float* dr = dpl + (long long)ir * W + x0;
                float4 dA = *reinterpret_cast<const float4*>(dr);
                float4 dB = *reinterpret_cast<const float4*>(dr + 4);
                float dv[8] = { dA.x, dA.y, dA.z, dA.w, dB.x, dB.y, dB.z, dB.w };

                float g[8], mean[8], var[8], del[8];
                #pragma unroll
                for (int i = 0; i < 8; ++i) {
                    g[i] = clampg(fmaf(BETA_P, dv[i], acc[i]));
                    float s  = sumP[off + i] + g[i];
                    float sq = fmaf(g[i], g[i], ssqP[off + i]);
                    mean[i] = s * inv;
                    var[i]  = fmaf(-mean[i], mean[i], sq * inv);
                    del[i]  = g[i] - dv[i];
                }
                *reinterpret_cast<float4*>(out + idx)                = make_float4(g[0], g[1], g[2], g[3]);
                *reinterpret_cast<float4*>(out + idx + 4)            = make_float4(g[4], g[5], g[6], g[7]);
                *reinterpret_cast<float4*>(out + NTOT + idx)         = make_float4(mean[0], mean[1], mean[2], mean[3]);
                *reinterpret_cast<float4*>(out + NTOT + idx + 4)     = make_float4(mean[4], mean[5], mean[6], mean[7]);
                *reinterpret_cast<float4*>(out + 2 * NTOT + idx)     = make_float4(var[0], var[1], var[2], var[3]);
                *reinterpret_cast<float4*>(out + 2 * NTOT + idx + 4) = make_float4(var[4], var[5], var[6], var[7]);
                *reinterpret_cast<float4*>(out + 3 * NTOT + idx)     = make_float4(del[0], del[1], del[2], del[3]);
                *reinterpret_cast<float4*>(out + 3 * NTOT + idx + 4) = make_float4(del[4], del[5], del[6], del[7]);
                *reinterpret_cast<float4*>(out + 4 * NTOT + idx)     = make_float4(del[0], del[1], del[2], del[3]);
                *reinterpret_cast<float4*>(out + 4 * NTOT + idx + 4) = make_float4(del[4], del[5], del[6], del[7]);
            }
        }
    }

    // no CTA may exit while a neighbor might still pull from its smem
    CLUSTER_BAR();
}

extern "C" void kernel_launch(void* const* d_in, const int* in_sizes, int n_in,
                              void* d_out, int out_size)
{
    const float* drive  = (const float*)d_in[0];   // [16,8,256,256] f32
    const float* Klocal = (const float*)d_in[1];   // [8,1,3,3] f32
    float* out = (float*)d_out;                    // 5 x [16,8,256,256] f32

    cudaFuncSetAttribute(cml_quad_kernel,
                         cudaFuncAttributeMaxDynamicSharedMemorySize, SMEM_BYTES);

    dim3 grid(NSTRIP, 8, 16);          // 4 strips (1 cluster/plane) x 8 ch x 16 b
    dim3 block(TXN, TYN);              // 512 threads
    cml_quad_kernel<<<grid, block, SMEM_BYTES>>>(drive, Klocal, out);
}